// round 1
// baseline (speedup 1.0000x reference)
#include <cuda_runtime.h>

#define TOKENS   8192      // B*N = 4*2048
#define DIM      1024
#define NE       8
#define HID      2730
#define HPAD     2736      // padded hidden: mult of 16, float4-aligned rows
#define NPAIR    (TOKENS * 2)

#define BM 64
#define BN 64
#define BK 16

// ---------------- device scratch (no allocations allowed) ----------------
__device__ int   g_count[NE];
__device__ int   g_pair;
__device__ int   g_tokens[NE][TOKENS];
__device__ float g_wts[NE][TOKENS];
__device__ int   g_slot[NE][TOKENS];
__device__ float g_probsum[NE];
__device__ float g_H[(size_t)NPAIR * HPAD];   // ~179 MB

// ---------------- zero output + reset counters ----------------
__global__ void zero_kernel(float* __restrict__ out, int n) {
    int i = blockIdx.x * blockDim.x + threadIdx.x;
    if (i < n) out[i] = 0.0f;
    if (blockIdx.x == 0) {
        if (threadIdx.x < NE) { g_count[threadIdx.x] = 0; g_probsum[threadIdx.x] = 0.0f; }
        if (threadIdx.x == NE) g_pair = 0;
    }
}

// ---------------- router: 1 warp per token ----------------
__global__ void router_kernel(const float* __restrict__ x,
                              const float* __restrict__ gw) {
    int warp = (blockIdx.x * blockDim.x + threadIdx.x) >> 5;
    int lane = threadIdx.x & 31;
    if (warp >= TOKENS) return;
    const float* xr = x + (size_t)warp * DIM;

    float acc[NE];
#pragma unroll
    for (int e = 0; e < NE; e++) acc[e] = 0.0f;

    for (int i = lane; i < DIM; i += 32) {
        float xv = xr[i];
#pragma unroll
        for (int e = 0; e < NE; e++) acc[e] = fmaf(xv, gw[e * DIM + i], acc[e]);
    }
#pragma unroll
    for (int e = 0; e < NE; e++) {
#pragma unroll
        for (int o = 16; o; o >>= 1) acc[e] += __shfl_xor_sync(0xffffffffu, acc[e], o);
    }
    if (lane == 0) {
        float m = acc[0];
#pragma unroll
        for (int e = 1; e < NE; e++) m = fmaxf(m, acc[e]);
        float p[NE]; float s = 0.0f;
#pragma unroll
        for (int e = 0; e < NE; e++) { p[e] = __expf(acc[e] - m); s += p[e]; }
        float inv = 1.0f / s;
#pragma unroll
        for (int e = 0; e < NE; e++) p[e] *= inv;

        // top-2 (first index wins ties, matching jax top_k)
        int i0 = 0;
#pragma unroll
        for (int e = 1; e < NE; e++) if (p[e] > p[i0]) i0 = e;
        int i1 = (i0 == 0) ? 1 : 0;
#pragma unroll
        for (int e = 0; e < NE; e++) if (e != i0 && p[e] > p[i1]) i1 = e;

        float s2 = p[i0] + p[i1];
        float w0 = p[i0] / s2;
        float w1n = p[i1] / s2;

        int pos0 = atomicAdd(&g_count[i0], 1);
        int sl0  = atomicAdd(&g_pair, 1);
        g_tokens[i0][pos0] = warp; g_wts[i0][pos0] = w0; g_slot[i0][pos0] = sl0;

        int pos1 = atomicAdd(&g_count[i1], 1);
        int sl1  = atomicAdd(&g_pair, 1);
        g_tokens[i1][pos1] = warp; g_wts[i1][pos1] = w1n; g_slot[i1][pos1] = sl1;

#pragma unroll
        for (int e = 0; e < NE; e++) atomicAdd(&g_probsum[e], p[e]);
    }
}

// ---------------- GEMM1: H = silu(X@w1^T) * (X@w3^T), per-expert grouped ----------------
__global__ __launch_bounds__(256) void gemm1_kernel(const float* __restrict__ x,
                                                    const float* __restrict__ w1,
                                                    const float* __restrict__ w3) {
    int e = blockIdx.z;
    int cnt = g_count[e];
    int m0 = blockIdx.y * BM;
    if (m0 >= cnt) return;
    int n0 = blockIdx.x * BN;

    __shared__ float Xs[BK][BM];
    __shared__ float W1s[BK][BN];
    __shared__ float W3s[BK][BN];

    int t  = threadIdx.x;
    int tm = t >> 4, tn = t & 15;     // 16x16 thread grid, 4x4 per thread
    int lr = t >> 2;                  // 0..63 load row
    int lk = (t & 3) << 2;            // 0,4,8,12 load k offset

    int mrow = m0 + lr;
    int tok  = (mrow < cnt) ? g_tokens[e][mrow] : g_tokens[e][0];
    const float* xrow = x + (size_t)tok * DIM;

    int nrow = n0 + lr;
    bool nvalid = (nrow < HID);
    const float* w1row = w1 + (size_t)e * HID * DIM + (size_t)(nvalid ? nrow : 0) * DIM;
    const float* w3row = w3 + (size_t)e * HID * DIM + (size_t)(nvalid ? nrow : 0) * DIM;

    float acc1[4][4], acc3[4][4];
#pragma unroll
    for (int i = 0; i < 4; i++)
#pragma unroll
        for (int j = 0; j < 4; j++) { acc1[i][j] = 0.0f; acc3[i][j] = 0.0f; }

    for (int k0 = 0; k0 < DIM; k0 += BK) {
        float4 xa = *(const float4*)&xrow[k0 + lk];
        float4 b1 = *(const float4*)&w1row[k0 + lk];
        float4 b3 = *(const float4*)&w3row[k0 + lk];
        if (!nvalid) { b1 = make_float4(0,0,0,0); b3 = make_float4(0,0,0,0); }

        __syncthreads();
        Xs[lk+0][lr] = xa.x; Xs[lk+1][lr] = xa.y; Xs[lk+2][lr] = xa.z; Xs[lk+3][lr] = xa.w;
        W1s[lk+0][lr] = b1.x; W1s[lk+1][lr] = b1.y; W1s[lk+2][lr] = b1.z; W1s[lk+3][lr] = b1.w;
        W3s[lk+0][lr] = b3.x; W3s[lk+1][lr] = b3.y; W3s[lk+2][lr] = b3.z; W3s[lk+3][lr] = b3.w;
        __syncthreads();

#pragma unroll
        for (int k = 0; k < BK; k++) {
            float4 a = *(const float4*)&Xs[k][tm * 4];
            float4 u = *(const float4*)&W1s[k][tn * 4];
            float4 v = *(const float4*)&W3s[k][tn * 4];
            float av[4] = {a.x, a.y, a.z, a.w};
            float uv[4] = {u.x, u.y, u.z, u.w};
            float vv[4] = {v.x, v.y, v.z, v.w};
#pragma unroll
            for (int i = 0; i < 4; i++)
#pragma unroll
                for (int j = 0; j < 4; j++) {
                    acc1[i][j] = fmaf(av[i], uv[j], acc1[i][j]);
                    acc3[i][j] = fmaf(av[i], vv[j], acc3[i][j]);
                }
        }
    }

    // epilogue: silu(a)*b into padded H scratch (pad cols [HID,HPAD) get 0)
#pragma unroll
    for (int i = 0; i < 4; i++) {
        int mr = m0 + tm * 4 + i;
        if (mr >= cnt) continue;
        int slot = g_slot[e][mr];
        float* hrow = g_H + (size_t)slot * HPAD;
#pragma unroll
        for (int j = 0; j < 4; j++) {
            int nc = n0 + tn * 4 + j;
            if (nc < HPAD) {
                float aa = acc1[i][j];
                float h = (nc < HID) ? (aa / (1.0f + __expf(-aa))) * acc3[i][j] : 0.0f;
                hrow[nc] = h;
            }
        }
    }
}

// ---------------- GEMM2: out += wt * (H @ w2^T) ----------------
__global__ __launch_bounds__(256) void gemm2_kernel(const float* __restrict__ w2,
                                                    float* __restrict__ out) {
    int e = blockIdx.z;
    int cnt = g_count[e];
    int m0 = blockIdx.y * BM;
    if (m0 >= cnt) return;
    int n0 = blockIdx.x * BN;

    __shared__ float Hs[BK][BM];
    __shared__ float Ws[BK][BN];

    int t  = threadIdx.x;
    int tm = t >> 4, tn = t & 15;
    int lr = t >> 2;
    int lk = (t & 3) << 2;

    int mrow = m0 + lr;
    int slot = (mrow < cnt) ? g_slot[e][mrow] : g_slot[e][0];
    const float* hrow = g_H + (size_t)slot * HPAD;

    int nrow = n0 + lr;   // always < 1024
    const float* wrow = w2 + (size_t)e * DIM * HID + (size_t)nrow * HID;

    float acc[4][4];
#pragma unroll
    for (int i = 0; i < 4; i++)
#pragma unroll
        for (int j = 0; j < 4; j++) acc[i][j] = 0.0f;

    for (int k0 = 0; k0 < HPAD; k0 += BK) {
        float4 ha = *(const float4*)&hrow[k0 + lk];
        float wv[4];
#pragma unroll
        for (int q = 0; q < 4; q++) {
            int kk = k0 + lk + q;
            wv[q] = (kk < HID) ? wrow[kk] : 0.0f;
        }
        __syncthreads();
        Hs[lk+0][lr] = ha.x; Hs[lk+1][lr] = ha.y; Hs[lk+2][lr] = ha.z; Hs[lk+3][lr] = ha.w;
        Ws[lk+0][lr] = wv[0]; Ws[lk+1][lr] = wv[1]; Ws[lk+2][lr] = wv[2]; Ws[lk+3][lr] = wv[3];
        __syncthreads();

#pragma unroll
        for (int k = 0; k < BK; k++) {
            float4 a = *(const float4*)&Hs[k][tm * 4];
            float4 b = *(const float4*)&Ws[k][tn * 4];
            float av[4] = {a.x, a.y, a.z, a.w};
            float bv[4] = {b.x, b.y, b.z, b.w};
#pragma unroll
            for (int i = 0; i < 4; i++)
#pragma unroll
                for (int j = 0; j < 4; j++)
                    acc[i][j] = fmaf(av[i], bv[j], acc[i][j]);
        }
    }

#pragma unroll
    for (int i = 0; i < 4; i++) {
        int mr = m0 + tm * 4 + i;
        if (mr >= cnt) continue;
        int tok  = g_tokens[e][mr];
        float wt = g_wts[e][mr];
        float* orow = out + (size_t)tok * DIM + n0;
#pragma unroll
        for (int j = 0; j < 4; j++)
            atomicAdd(&orow[tn * 4 + j], wt * acc[i][j]);
    }
}

// ---------------- aux loss ----------------
__global__ void aux_kernel(float* __restrict__ out, int out_size) {
    if (threadIdx.x == 0 && blockIdx.x == 0) {
        float s = 0.0f;
#pragma unroll
        for (int e = 0; e < NE; e++) {
            float tpe = g_probsum[e] / (float)TOKENS;
            float d = tpe - (1.0f / NE);
            s += d * d;
        }
        float aux = 0.01f * (s / (float)NE);
        if (out_size > TOKENS * DIM) out[TOKENS * DIM] = aux;
    }
}

// ---------------- launch ----------------
extern "C" void kernel_launch(void* const* d_in, const int* in_sizes, int n_in,
                              void* d_out, int out_size) {
    const float* x  = (const float*)d_in[0];
    const float* gw = (const float*)d_in[1];
    const float* w1 = (const float*)d_in[2];
    const float* w2 = (const float*)d_in[3];
    const float* w3 = (const float*)d_in[4];
    float* out = (float*)d_out;

    int nzero = out_size < TOKENS * DIM ? out_size : TOKENS * DIM;
    zero_kernel<<<(nzero + 255) / 256, 256>>>(out, nzero);
    router_kernel<<<TOKENS / 8, 256>>>(x, gw);

    dim3 g1((HID + BN - 1) / BN, TOKENS / BM, NE);
    gemm1_kernel<<<g1, 256>>>(x, w1, w3);

    dim3 g2(DIM / BN, TOKENS / BM, NE);
    gemm2_kernel<<<g2, 256>>>(w2, out);

    aux_kernel<<<1, 32>>>(out, out_size);
}

// round 3
// speedup vs baseline: 3.3523x; 3.3523x over previous
#include <cuda_runtime.h>
#include <cuda_bf16.h>
#include <cstdint>

#define TOKENS 8192
#define DIM    1024
#define NE     8
#define HID    2730
#define HP     2816            // HID padded (multiple of 128)
#define NPAIR  (TOKENS*2)
#define HROWS  (NPAIR + 128)

#define BM  128
#define BKC 64                 // bf16 K per chunk = 128B row
#define SWZ(o) ((o) ^ (((o) >> 3) & 0x70))

#define STAGE1 65536           // GEMM1: Ah,Al(16K ea) + 4 W tiles(8K ea)
#define STAGE2 65536           // GEMM2: Ah,Al(16K ea) + Bh,Bl(16K ea)

// ---------------- device scratch ----------------
__device__ int   g_count[NE];
__device__ int   g_off[NE];
__device__ int   g_tokens[NE][TOKENS];
__device__ float g_wts[NE][TOKENS];
__device__ float g_probsum[NE];

__device__ __nv_bfloat16 g_XH[TOKENS*DIM];
__device__ __nv_bfloat16 g_XL[TOKENS*DIM];
__device__ __nv_bfloat16 g_W1H[NE*HP*DIM];
__device__ __nv_bfloat16 g_W1L[NE*HP*DIM];
__device__ __nv_bfloat16 g_W3H[NE*HP*DIM];
__device__ __nv_bfloat16 g_W3L[NE*HP*DIM];
__device__ __nv_bfloat16 g_W2H[NE*DIM*HP];
__device__ __nv_bfloat16 g_W2L[NE*DIM*HP];
__device__ __nv_bfloat16 g_HH[(size_t)HROWS*HP];
__device__ __nv_bfloat16 g_HL[(size_t)HROWS*HP];

// ---------------- helpers ----------------
__device__ __forceinline__ uint32_t s2u(const void* p) {
    uint32_t a;
    asm("{ .reg .u64 t; cvta.to.shared.u64 t, %1; cvt.u32.u64 %0, t; }" : "=r"(a) : "l"(p));
    return a;
}
__device__ __forceinline__ void cpa16(uint32_t dst, const void* src) {
    asm volatile("cp.async.cg.shared.global [%0], [%1], 16;" :: "r"(dst), "l"(src));
}
__device__ __forceinline__ void cp_commit() {
    asm volatile("cp.async.commit_group;" ::: "memory");
}
__device__ __forceinline__ void cp_wait1() {
    asm volatile("cp.async.wait_group 1;" ::: "memory");
}
__device__ __forceinline__ void ldm4(uint32_t* r, uint32_t addr) {
    asm volatile("ldmatrix.sync.aligned.m8n8.x4.shared.b16 {%0,%1,%2,%3}, [%4];"
                 : "=r"(r[0]), "=r"(r[1]), "=r"(r[2]), "=r"(r[3]) : "r"(addr));
}
__device__ __forceinline__ void mma16816(float* c, const uint32_t* a, const uint32_t* b) {
    asm volatile("mma.sync.aligned.m16n8k16.row.col.f32.bf16.bf16.f32 "
                 "{%0,%1,%2,%3}, {%4,%5,%6,%7}, {%8,%9}, {%0,%1,%2,%3};"
                 : "+f"(c[0]), "+f"(c[1]), "+f"(c[2]), "+f"(c[3])
                 : "r"(a[0]), "r"(a[1]), "r"(a[2]), "r"(a[3]), "r"(b[0]), "r"(b[1]));
}
__device__ __forceinline__ uint32_t pk(__nv_bfloat16 a, __nv_bfloat16 b) {
    return ((uint32_t)__bfloat16_as_ushort(b) << 16) | (uint32_t)__bfloat16_as_ushort(a);
}
__device__ __forceinline__ void redadd(float* p, float v) {
    asm volatile("red.global.add.f32 [%0], %1;" :: "l"(p), "f"(v) : "memory");
}

// ---------------- small kernels ----------------
__global__ void zero_kernel(float* __restrict__ out, int n) {
    int i = blockIdx.x * blockDim.x + threadIdx.x;
    if (i < n) out[i] = 0.0f;
    if (blockIdx.x == 0 && threadIdx.x < NE) {
        g_count[threadIdx.x] = 0;
        g_probsum[threadIdx.x] = 0.0f;
    }
}

__global__ void convx_kernel(const float* __restrict__ x) {
    int i = blockIdx.x * 256 + threadIdx.x;
    float v = x[i];
    __nv_bfloat16 h = __float2bfloat16(v);
    g_XH[i] = h;
    g_XL[i] = __float2bfloat16(v - __bfloat162float(h));
}

__global__ void convw13_kernel(const float* __restrict__ w1, const float* __restrict__ w3) {
    int i = blockIdx.x * 256 + threadIdx.x;       // over NE*HP*DIM
    int col  = i & (DIM - 1);
    int rowe = i >> 10;
    int row  = rowe % HP;
    int e    = rowe / HP;
    float v1 = 0.0f, v3 = 0.0f;
    if (row < HID) {
        size_t si = ((size_t)e * HID + row) * DIM + col;
        v1 = w1[si]; v3 = w3[si];
    }
    __nv_bfloat16 h1 = __float2bfloat16(v1);
    __nv_bfloat16 h3 = __float2bfloat16(v3);
    g_W1H[i] = h1; g_W1L[i] = __float2bfloat16(v1 - __bfloat162float(h1));
    g_W3H[i] = h3; g_W3L[i] = __float2bfloat16(v3 - __bfloat162float(h3));
}

__global__ void convw2_kernel(const float* __restrict__ w2) {
    int i = blockIdx.x * 256 + threadIdx.x;       // over NE*DIM*HP
    int col  = i % HP;
    int rowd = i / HP;
    float v = 0.0f;
    if (col < HID) v = w2[(size_t)rowd * HID + col];
    __nv_bfloat16 h = __float2bfloat16(v);
    g_W2H[i] = h;
    g_W2L[i] = __float2bfloat16(v - __bfloat162float(h));
}

__global__ void router_kernel(const float* __restrict__ x, const float* __restrict__ gw) {
    int warp = (blockIdx.x * blockDim.x + threadIdx.x) >> 5;
    int lane = threadIdx.x & 31;
    if (warp >= TOKENS) return;
    const float* xr = x + (size_t)warp * DIM;
    float acc[NE];
#pragma unroll
    for (int e = 0; e < NE; e++) acc[e] = 0.0f;
    for (int i = lane; i < DIM; i += 32) {
        float xv = xr[i];
#pragma unroll
        for (int e = 0; e < NE; e++) acc[e] = fmaf(xv, gw[e * DIM + i], acc[e]);
    }
#pragma unroll
    for (int e = 0; e < NE; e++)
#pragma unroll
        for (int o = 16; o; o >>= 1) acc[e] += __shfl_xor_sync(0xffffffffu, acc[e], o);
    if (lane == 0) {
        float m = acc[0];
#pragma unroll
        for (int e = 1; e < NE; e++) m = fmaxf(m, acc[e]);
        float p[NE]; float s = 0.0f;
#pragma unroll
        for (int e = 0; e < NE; e++) { p[e] = __expf(acc[e] - m); s += p[e]; }
        float inv = 1.0f / s;
#pragma unroll
        for (int e = 0; e < NE; e++) p[e] *= inv;
        int i0 = 0;
#pragma unroll
        for (int e = 1; e < NE; e++) if (p[e] > p[i0]) i0 = e;
        int i1 = (i0 == 0) ? 1 : 0;
#pragma unroll
        for (int e = 0; e < NE; e++) if (e != i0 && p[e] > p[i1]) i1 = e;
        float s2 = p[i0] + p[i1];
        int pos0 = atomicAdd(&g_count[i0], 1);
        g_tokens[i0][pos0] = warp; g_wts[i0][pos0] = p[i0] / s2;
        int pos1 = atomicAdd(&g_count[i1], 1);
        g_tokens[i1][pos1] = warp; g_wts[i1][pos1] = p[i1] / s2;
#pragma unroll
        for (int e = 0; e < NE; e++) atomicAdd(&g_probsum[e], p[e]);
    }
}

__global__ void scan_kernel() {
    if (threadIdx.x == 0) {
        int s = 0;
#pragma unroll
        for (int e = 0; e < NE; e++) { g_off[e] = s; s += g_count[e]; }
    }
}

__global__ void aux_kernel(float* __restrict__ out, int out_size) {
    if (threadIdx.x == 0 && blockIdx.x == 0) {
        float s = 0.0f;
#pragma unroll
        for (int e = 0; e < NE; e++) {
            float tpe = g_probsum[e] / (float)TOKENS;
            float d = tpe - (1.0f / NE);
            s += d * d;
        }
        if (out_size > TOKENS * DIM) out[TOKENS * DIM] = 0.01f * (s / (float)NE);
    }
}

// ---------------- GEMM1: H = silu(X@w1^T) * (X@w3^T) ----------------
// CTA: 128 M x 64 N(H cols), K=DIM. Warps 4(m) x 2(n), warp tile 32x32, dual output.
__global__ __launch_bounds__(256, 1) void gemm1_kernel() {
    int e = blockIdx.z;
    int cnt = g_count[e];
    int m0 = blockIdx.y * BM;
    if (m0 >= cnt) return;
    int n0 = blockIdx.x * 64;

    extern __shared__ char smraw[];
    uint32_t smb = s2u(smraw);
    int tid = threadIdx.x, wid = tid >> 5, lane = tid & 31;

    // --- loader geometry: 16B chunks, row = rA(+32i), col16 = tid&7 ---
    int rA = tid >> 3, c16 = tid & 7;
    uint32_t dstA[4], dstB[2];
    const char* sAh[4]; const char* sAl[4];
    const char* sB[4][2];   // w1h,w1l,w3h,w3l
#pragma unroll
    for (int i = 0; i < 4; i++) {
        int r = rA + 32 * i;
        uint32_t off = (uint32_t)(r * 128 + c16 * 16);
        dstA[i] = SWZ(off);
        int mi = m0 + r; if (mi >= cnt) mi = cnt - 1;
        int tok = g_tokens[e][mi];
        size_t ao = ((size_t)tok * DIM + c16 * 8) * 2;
        sAh[i] = (const char*)g_XH + ao;
        sAl[i] = (const char*)g_XL + ao;
    }
#pragma unroll
    for (int i = 0; i < 2; i++) {
        int r = rA + 32 * i;                    // 0..63
        uint32_t off = (uint32_t)(r * 128 + c16 * 16);
        dstB[i] = SWZ(off);
        size_t wo = (((size_t)e * HP + n0 + r) * DIM + c16 * 8) * 2;
        sB[0][i] = (const char*)g_W1H + wo;
        sB[1][i] = (const char*)g_W1L + wo;
        sB[2][i] = (const char*)g_W3H + wo;
        sB[3][i] = (const char*)g_W3L + wo;
    }

    auto load = [&](int kc, int s) {
        uint32_t base = smb + s * STAGE1;
        size_t ko = (size_t)kc * 128;           // 64 bf16 = 128 bytes
#pragma unroll
        for (int i = 0; i < 4; i++) {
            cpa16(base + dstA[i], sAh[i] + ko);
            cpa16(base + 16384 + dstA[i], sAl[i] + ko);
        }
#pragma unroll
        for (int i = 0; i < 2; i++) {
#pragma unroll
            for (int t = 0; t < 4; t++)
                cpa16(base + 32768 + t * 8192 + dstB[i], sB[t][i] + ko);
        }
        cp_commit();
    };

    float c1[2][4][4], c3[2][4][4];
#pragma unroll
    for (int a = 0; a < 2; a++)
#pragma unroll
        for (int b = 0; b < 4; b++)
#pragma unroll
            for (int q = 0; q < 4; q++) { c1[a][b][q] = 0.0f; c3[a][b][q] = 0.0f; }

    int m0w = (wid & 3) * 32;
    int n0w = (wid >> 2) * 32;
    const int NC = DIM / BKC;                   // 16

    load(0, 0);
    load(1, 1);

#pragma unroll 1
    for (int c = 0; c < NC; c++) {
        cp_wait1();
        __syncthreads();
        uint32_t bA = smb + (c & 1) * STAGE1;
        uint32_t bAh = bA, bAl = bA + 16384;
        uint32_t b1h = bA + 32768, b1l = bA + 40960;
        uint32_t b3h = bA + 49152, b3l = bA + 57344;
#pragma unroll
        for (int ks = 0; ks < 4; ks++) {
            int k0b = ks * 32;
            uint32_t ah[2][4], al_[2][4];
#pragma unroll
            for (int mg = 0; mg < 2; mg++) {
                int row = m0w + mg * 16 + (lane & 15);
                uint32_t off = SWZ((uint32_t)(row * 128 + k0b + (lane >> 4) * 16));
                ldm4(ah[mg], bAh + off);
                ldm4(al_[mg], bAl + off);
            }
#pragma unroll
            for (int g = 0; g < 2; g++) {
                int nrow = n0w + g * 16 + (lane & 7) + (lane >> 4) * 8;
                uint32_t boff = SWZ((uint32_t)(nrow * 128 + k0b + ((lane >> 3) & 1) * 16));
                uint32_t f1h[4], f1l[4], f3h[4], f3l[4];
                ldm4(f1h, b1h + boff); ldm4(f1l, b1l + boff);
                ldm4(f3h, b3h + boff); ldm4(f3l, b3l + boff);
#pragma unroll
                for (int mg = 0; mg < 2; mg++) {
#pragma unroll
                    for (int sub = 0; sub < 2; sub++) {
                        int ng = g * 2 + sub;
                        mma16816(c1[mg][ng], ah[mg],  f1h + sub * 2);
                        mma16816(c1[mg][ng], ah[mg],  f1l + sub * 2);
                        mma16816(c1[mg][ng], al_[mg], f1h + sub * 2);
                        mma16816(c3[mg][ng], ah[mg],  f3h + sub * 2);
                        mma16816(c3[mg][ng], ah[mg],  f3l + sub * 2);
                        mma16816(c3[mg][ng], al_[mg], f3h + sub * 2);
                    }
                }
            }
        }
        __syncthreads();
        if (c + 2 < NC) load(c + 2, c & 1);
        else cp_commit();                       // keep group count stable
    }

    // --- fused SwiGLU epilogue -> bf16 hi/lo H ---
    int goff = g_off[e];
    int t4 = lane >> 2, cpair = (lane & 3) * 2;
#pragma unroll
    for (int mg = 0; mg < 2; mg++) {
#pragma unroll
        for (int half = 0; half < 2; half++) {
            int mi = m0 + m0w + mg * 16 + half * 8 + t4;
            if (mi >= cnt) continue;
            size_t hb = (size_t)(goff + mi) * HP;
#pragma unroll
            for (int ng = 0; ng < 4; ng++) {
                int col = n0 + n0w + ng * 8 + cpair;
                float a0 = c1[mg][ng][half * 2 + 0];
                float a1 = c1[mg][ng][half * 2 + 1];
                float b0 = c3[mg][ng][half * 2 + 0];
                float b1 = c3[mg][ng][half * 2 + 1];
                float h0 = (a0 / (1.0f + __expf(-a0))) * b0;
                float h1 = (a1 / (1.0f + __expf(-a1))) * b1;
                __nv_bfloat16 h0h = __float2bfloat16(h0);
                __nv_bfloat16 h1h = __float2bfloat16(h1);
                __nv_bfloat16 h0l = __float2bfloat16(h0 - __bfloat162float(h0h));
                __nv_bfloat16 h1l = __float2bfloat16(h1 - __bfloat162float(h1h));
                *(uint32_t*)(g_HH + hb + col) = pk(h0h, h1h);
                *(uint32_t*)(g_HL + hb + col) = pk(h0l, h1l);
            }
        }
    }
}

// ---------------- GEMM2: out += wt * (H @ w2^T) ----------------
// CTA: 128 M x 128 N, K=HP. Warps 4(m) x 2(n), warp tile 32x64.
__global__ __launch_bounds__(256, 1) void gemm2_kernel(float* __restrict__ out) {
    int e = blockIdx.z;
    int cnt = g_count[e];
    int m0 = blockIdx.y * BM;
    if (m0 >= cnt) return;
    int n0 = blockIdx.x * 128;

    extern __shared__ char smraw[];
    uint32_t smb = s2u(smraw);
    int tid = threadIdx.x, wid = tid >> 5, lane = tid & 31;
    int off_e = g_off[e];

    int rA = tid >> 3, c16 = tid & 7;
    uint32_t dstA[4];
    const char* sAh[4]; const char* sAl[4];
    const char* sBh[4]; const char* sBl[4];
#pragma unroll
    for (int i = 0; i < 4; i++) {
        int r = rA + 32 * i;
        uint32_t off = (uint32_t)(r * 128 + c16 * 16);
        dstA[i] = SWZ(off);
        int mi = m0 + r; if (mi >= cnt) mi = cnt - 1;
        size_t ao = (((size_t)(off_e + mi)) * HP + c16 * 8) * 2;
        sAh[i] = (const char*)g_HH + ao;
        sAl[i] = (const char*)g_HL + ao;
        size_t wo = (((size_t)e * DIM + n0 + r) * HP + c16 * 8) * 2;
        sBh[i] = (const char*)g_W2H + wo;
        sBl[i] = (const char*)g_W2L + wo;
    }

    auto load = [&](int kc, int s) {
        uint32_t base = smb + s * STAGE2;
        size_t ko = (size_t)kc * 128;
#pragma unroll
        for (int i = 0; i < 4; i++) {
            cpa16(base + dstA[i], sAh[i] + ko);
            cpa16(base + 16384 + dstA[i], sAl[i] + ko);
            cpa16(base + 32768 + dstA[i], sBh[i] + ko);
            cpa16(base + 49152 + dstA[i], sBl[i] + ko);
        }
        cp_commit();
    };

    float cc[2][8][4];
#pragma unroll
    for (int a = 0; a < 2; a++)
#pragma unroll
        for (int b = 0; b < 8; b++)
#pragma unroll
            for (int q = 0; q < 4; q++) cc[a][b][q] = 0.0f;

    int m0w = (wid & 3) * 32;
    int n0w = (wid >> 2) * 64;
    const int NC = HP / BKC;                    // 44

    load(0, 0);
    load(1, 1);

#pragma unroll 1
    for (int c = 0; c < NC; c++) {
        cp_wait1();
        __syncthreads();
        uint32_t bA = smb + (c & 1) * STAGE2;
        uint32_t bAh = bA, bAl = bA + 16384;
        uint32_t bBh = bA + 32768, bBl = bA + 49152;
#pragma unroll
        for (int ks = 0; ks < 4; ks++) {
            int k0b = ks * 32;
            uint32_t ah[2][4], al_[2][4];
#pragma unroll
            for (int mg = 0; mg < 2; mg++) {
                int row = m0w + mg * 16 + (lane & 15);
                uint32_t off = SWZ((uint32_t)(row * 128 + k0b + (lane >> 4) * 16));
                ldm4(ah[mg], bAh + off);
                ldm4(al_[mg], bAl + off);
            }
#pragma unroll
            for (int g = 0; g < 4; g++) {
                int nrow = n0w + g * 16 + (lane & 7) + (lane >> 4) * 8;
                uint32_t boff = SWZ((uint32_t)(nrow * 128 + k0b + ((lane >> 3) & 1) * 16));
                uint32_t fh[4], fl[4];
                ldm4(fh, bBh + boff); ldm4(fl, bBl + boff);
#pragma unroll
                for (int mg = 0; mg < 2; mg++) {
#pragma unroll
                    for (int sub = 0; sub < 2; sub++) {
                        int ng = g * 2 + sub;
                        mma16816(cc[mg][ng], ah[mg],  fh + sub * 2);
                        mma16816(cc[mg][ng], ah[mg],  fl + sub * 2);
                        mma16816(cc[mg][ng], al_[mg], fh + sub * 2);
                    }
                }
            }
        }
        __syncthreads();
        if (c + 2 < NC) load(c + 2, c & 1);
        else cp_commit();
    }

    // --- epilogue: out[tok] += wt * acc (REDG, no return) ---
    int t4 = lane >> 2, cpair = (lane & 3) * 2;
#pragma unroll
    for (int mg = 0; mg < 2; mg++) {
#pragma unroll
        for (int half = 0; half < 2; half++) {
            int mi = m0 + m0w + mg * 16 + half * 8 + t4;
            if (mi >= cnt) continue;
            int tok = g_tokens[e][mi];
            float wt = g_wts[e][mi];
            float* orow = out + (size_t)tok * DIM;
#pragma unroll
            for (int ng = 0; ng < 8; ng++) {
                int col = n0 + n0w + ng * 8 + cpair;
                redadd(&orow[col],     wt * cc[mg][ng][half * 2 + 0]);
                redadd(&orow[col + 1], wt * cc[mg][ng][half * 2 + 1]);
            }
        }
    }
}

// ---------------- launch ----------------
extern "C" void kernel_launch(void* const* d_in, const int* in_sizes, int n_in,
                              void* d_out, int out_size) {
    const float* x  = (const float*)d_in[0];
    const float* gw = (const float*)d_in[1];
    const float* w1 = (const float*)d_in[2];
    const float* w2 = (const float*)d_in[3];
    const float* w3 = (const float*)d_in[4];
    float* out = (float*)d_out;

    cudaFuncSetAttribute(gemm1_kernel, cudaFuncAttributeMaxDynamicSharedMemorySize, 2 * STAGE1);
    cudaFuncSetAttribute(gemm2_kernel, cudaFuncAttributeMaxDynamicSharedMemorySize, 2 * STAGE2);

    int nzero = out_size < TOKENS * DIM ? out_size : TOKENS * DIM;
    zero_kernel<<<(nzero + 255) / 256, 256>>>(out, nzero);
    convx_kernel<<<(TOKENS * DIM) / 256, 256>>>(x);
    convw13_kernel<<<(NE * HP * DIM) / 256, 256>>>(w1, w3);
    convw2_kernel<<<(NE * DIM * HP) / 256, 256>>>(w2);
    router_kernel<<<TOKENS * 32 / 256, 256>>>(x, gw);
    scan_kernel<<<1, 32>>>();

    dim3 g1(HP / 64, TOKENS / BM, NE);
    gemm1_kernel<<<g1, 256, 2 * STAGE1>>>();

    dim3 g2(DIM / 128, TOKENS / BM, NE);
    gemm2_kernel<<<g2, 256, 2 * STAGE2>>>(out);

    aux_kernel<<<1, 32>>>(out, out_size);
}

// round 4
// speedup vs baseline: 3.4582x; 1.0316x over previous
#include <cuda_runtime.h>
#include <cuda_bf16.h>
#include <cstdint>

#define TOKENS 8192
#define DIM    1024
#define NE     8
#define HID    2730
#define HP     2816            // HID padded (multiple of 128)
#define NPAIR  (TOKENS*2)
#define HROWS  (NPAIR + 128)

#define BM  128
#define BKC 64                 // bf16 K per chunk = 128B row
#define SWZ(o) ((o) ^ (((o) >> 3) & 0x70))

#define STAGE1 65536
#define STAGE2 65536
#define NSTG   3

// ---------------- device scratch ----------------
__device__ int   g_count[NE];
__device__ int   g_off[NE];
__device__ int   g_tokens[NE][TOKENS];
__device__ float g_wts[NE][TOKENS];
__device__ float g_probsum[NE];

__device__ __nv_bfloat16 g_XH[TOKENS*DIM];
__device__ __nv_bfloat16 g_XL[TOKENS*DIM];
__device__ __nv_bfloat16 g_W1H[NE*HP*DIM];
__device__ __nv_bfloat16 g_W1L[NE*HP*DIM];
__device__ __nv_bfloat16 g_W3H[NE*HP*DIM];
__device__ __nv_bfloat16 g_W3L[NE*HP*DIM];
__device__ __nv_bfloat16 g_W2H[NE*DIM*HP];
__device__ __nv_bfloat16 g_W2L[NE*DIM*HP];
__device__ __nv_bfloat16 g_HH[(size_t)HROWS*HP];
__device__ __nv_bfloat16 g_HL[(size_t)HROWS*HP];

// ---------------- helpers ----------------
__device__ __forceinline__ uint32_t s2u(const void* p) {
    uint32_t a;
    asm("{ .reg .u64 t; cvta.to.shared.u64 t, %1; cvt.u32.u64 %0, t; }" : "=r"(a) : "l"(p));
    return a;
}
__device__ __forceinline__ void cpa16(uint32_t dst, const void* src) {
    asm volatile("cp.async.cg.shared.global [%0], [%1], 16;" :: "r"(dst), "l"(src));
}
__device__ __forceinline__ void cp_commit() {
    asm volatile("cp.async.commit_group;" ::: "memory");
}
__device__ __forceinline__ void cp_wait2() {
    asm volatile("cp.async.wait_group 2;" ::: "memory");
}
__device__ __forceinline__ void ldm4(uint32_t* r, uint32_t addr) {
    asm volatile("ldmatrix.sync.aligned.m8n8.x4.shared.b16 {%0,%1,%2,%3}, [%4];"
                 : "=r"(r[0]), "=r"(r[1]), "=r"(r[2]), "=r"(r[3]) : "r"(addr));
}
__device__ __forceinline__ void mma16816(float* c, const uint32_t* a, const uint32_t* b) {
    asm volatile("mma.sync.aligned.m16n8k16.row.col.f32.bf16.bf16.f32 "
                 "{%0,%1,%2,%3}, {%4,%5,%6,%7}, {%8,%9}, {%0,%1,%2,%3};"
                 : "+f"(c[0]), "+f"(c[1]), "+f"(c[2]), "+f"(c[3])
                 : "r"(a[0]), "r"(a[1]), "r"(a[2]), "r"(a[3]), "r"(b[0]), "r"(b[1]));
}
__device__ __forceinline__ uint32_t pk(__nv_bfloat16 a, __nv_bfloat16 b) {
    return ((uint32_t)__bfloat16_as_ushort(b) << 16) | (uint32_t)__bfloat16_as_ushort(a);
}
__device__ __forceinline__ void redadd(float* p, float v) {
    asm volatile("red.global.add.f32 [%0], %1;" :: "l"(p), "f"(v) : "memory");
}
// split a float4 into hi/lo bf16x4 packed as uint2
__device__ __forceinline__ void split4(float4 v, uint2& hi, uint2& lo) {
    __nv_bfloat16 h0 = __float2bfloat16(v.x), h1 = __float2bfloat16(v.y);
    __nv_bfloat16 h2 = __float2bfloat16(v.z), h3 = __float2bfloat16(v.w);
    __nv_bfloat16 l0 = __float2bfloat16(v.x - __bfloat162float(h0));
    __nv_bfloat16 l1 = __float2bfloat16(v.y - __bfloat162float(h1));
    __nv_bfloat16 l2 = __float2bfloat16(v.z - __bfloat162float(h2));
    __nv_bfloat16 l3 = __float2bfloat16(v.w - __bfloat162float(h3));
    hi = make_uint2(pk(h0, h1), pk(h2, h3));
    lo = make_uint2(pk(l0, l1), pk(l2, l3));
}

// ---------------- small kernels ----------------
__global__ void zero_kernel(float* __restrict__ out, int n) {
    int i = blockIdx.x * blockDim.x + threadIdx.x;
    if (i < n) out[i] = 0.0f;
    if (blockIdx.x == 0 && threadIdx.x < NE) {
        g_count[threadIdx.x] = 0;
        g_probsum[threadIdx.x] = 0.0f;
    }
}

__global__ void convx_kernel(const float* __restrict__ x) {
    int i = blockIdx.x * 256 + threadIdx.x;          // over TOKENS*DIM/4
    float4 v = ((const float4*)x)[i];
    uint2 hi, lo;
    split4(v, hi, lo);
    ((uint2*)g_XH)[i] = hi;
    ((uint2*)g_XL)[i] = lo;
}

__global__ void convw13_kernel(const float* __restrict__ w1, const float* __restrict__ w3) {
    int i = blockIdx.x * 256 + threadIdx.x;          // over NE*HP*DIM/4
    int c4   = i & (DIM / 4 - 1);
    int rowe = i >> 8;                               // e*HP + row
    int row  = rowe % HP;                            // constant div -> mulhi
    int e    = rowe / HP;
    float4 v1 = make_float4(0,0,0,0), v3 = make_float4(0,0,0,0);
    if (row < HID) {
        size_t si = (((size_t)e * HID + row) * DIM) / 4 + c4;
        v1 = ((const float4*)w1)[si];
        v3 = ((const float4*)w3)[si];
    }
    uint2 h, l;
    split4(v1, h, l); ((uint2*)g_W1H)[i] = h; ((uint2*)g_W1L)[i] = l;
    split4(v3, h, l); ((uint2*)g_W3H)[i] = h; ((uint2*)g_W3L)[i] = l;
}

__global__ void convw2_kernel(const float* __restrict__ w2) {
    int i = blockIdx.x * 256 + threadIdx.x;          // over NE*DIM*HP/4
    int c4   = i % (HP / 4);
    int rowd = i / (HP / 4);                         // e*DIM + d
    int col = c4 * 4;
    float4 v = make_float4(0,0,0,0);
    const float* src = w2 + (size_t)rowd * HID + col;
    if (col + 3 < HID) {
        v.x = src[0]; v.y = src[1]; v.z = src[2]; v.w = src[3];
    } else if (col < HID) {
        v.x = src[0];
        if (col + 1 < HID) v.y = src[1];
        // HID=2730, col pattern: boundary chunk col=2728 -> 2 valid
    }
    uint2 h, l;
    split4(v, h, l);
    ((uint2*)g_W2H)[i] = h;
    ((uint2*)g_W2L)[i] = l;
}

__global__ void router_kernel(const float* __restrict__ x, const float* __restrict__ gw) {
    int warp = (blockIdx.x * blockDim.x + threadIdx.x) >> 5;
    int lane = threadIdx.x & 31;
    if (warp >= TOKENS) return;
    const float* xr = x + (size_t)warp * DIM;
    float acc[NE];
#pragma unroll
    for (int e = 0; e < NE; e++) acc[e] = 0.0f;
    for (int i = lane; i < DIM; i += 32) {
        float xv = xr[i];
#pragma unroll
        for (int e = 0; e < NE; e++) acc[e] = fmaf(xv, gw[e * DIM + i], acc[e]);
    }
#pragma unroll
    for (int e = 0; e < NE; e++)
#pragma unroll
        for (int o = 16; o; o >>= 1) acc[e] += __shfl_xor_sync(0xffffffffu, acc[e], o);
    if (lane == 0) {
        float m = acc[0];
#pragma unroll
        for (int e = 1; e < NE; e++) m = fmaxf(m, acc[e]);
        float p[NE]; float s = 0.0f;
#pragma unroll
        for (int e = 0; e < NE; e++) { p[e] = __expf(acc[e] - m); s += p[e]; }
        float inv = 1.0f / s;
#pragma unroll
        for (int e = 0; e < NE; e++) p[e] *= inv;
        int i0 = 0;
#pragma unroll
        for (int e = 1; e < NE; e++) if (p[e] > p[i0]) i0 = e;
        int i1 = (i0 == 0) ? 1 : 0;
#pragma unroll
        for (int e = 0; e < NE; e++) if (e != i0 && p[e] > p[i1]) i1 = e;
        float s2 = p[i0] + p[i1];
        int pos0 = atomicAdd(&g_count[i0], 1);
        g_tokens[i0][pos0] = warp; g_wts[i0][pos0] = p[i0] / s2;
        int pos1 = atomicAdd(&g_count[i1], 1);
        g_tokens[i1][pos1] = warp; g_wts[i1][pos1] = p[i1] / s2;
#pragma unroll
        for (int e = 0; e < NE; e++) atomicAdd(&g_probsum[e], p[e]);
    }
}

__global__ void scan_kernel() {
    if (threadIdx.x == 0) {
        int s = 0;
#pragma unroll
        for (int e = 0; e < NE; e++) { g_off[e] = s; s += g_count[e]; }
    }
}

__global__ void aux_kernel(float* __restrict__ out, int out_size) {
    if (threadIdx.x == 0 && blockIdx.x == 0) {
        float s = 0.0f;
#pragma unroll
        for (int e = 0; e < NE; e++) {
            float tpe = g_probsum[e] / (float)TOKENS;
            float d = tpe - (1.0f / NE);
            s += d * d;
        }
        if (out_size > TOKENS * DIM) out[TOKENS * DIM] = 0.01f * (s / (float)NE);
    }
}

// ---------------- GEMM1: H = silu(X@w1^T) * (X@w3^T) ----------------
__global__ __launch_bounds__(256, 1) void gemm1_kernel() {
    int e = blockIdx.z;
    int cnt = g_count[e];
    int m0 = blockIdx.y * BM;
    if (m0 >= cnt) return;
    int n0 = blockIdx.x * 64;

    extern __shared__ char smraw[];
    uint32_t smb = s2u(smraw);
    int tid = threadIdx.x, wid = tid >> 5, lane = tid & 31;

    int rA = tid >> 3, c16 = tid & 7;
    uint32_t dstA[4], dstB[2];
    const char* sAh[4]; const char* sAl[4];
    const char* sB[4][2];
#pragma unroll
    for (int i = 0; i < 4; i++) {
        int r = rA + 32 * i;
        uint32_t off = (uint32_t)(r * 128 + c16 * 16);
        dstA[i] = SWZ(off);
        int mi = m0 + r; if (mi >= cnt) mi = cnt - 1;
        int tok = g_tokens[e][mi];
        size_t ao = ((size_t)tok * DIM + c16 * 8) * 2;
        sAh[i] = (const char*)g_XH + ao;
        sAl[i] = (const char*)g_XL + ao;
    }
#pragma unroll
    for (int i = 0; i < 2; i++) {
        int r = rA + 32 * i;
        uint32_t off = (uint32_t)(r * 128 + c16 * 16);
        dstB[i] = SWZ(off);
        size_t wo = (((size_t)e * HP + n0 + r) * DIM + c16 * 8) * 2;
        sB[0][i] = (const char*)g_W1H + wo;
        sB[1][i] = (const char*)g_W1L + wo;
        sB[2][i] = (const char*)g_W3H + wo;
        sB[3][i] = (const char*)g_W3L + wo;
    }

    auto load = [&](int kc, int s) {
        uint32_t base = smb + s * STAGE1;
        size_t ko = (size_t)kc * 128;
#pragma unroll
        for (int i = 0; i < 4; i++) {
            cpa16(base + dstA[i], sAh[i] + ko);
            cpa16(base + 16384 + dstA[i], sAl[i] + ko);
        }
#pragma unroll
        for (int i = 0; i < 2; i++) {
#pragma unroll
            for (int t = 0; t < 4; t++)
                cpa16(base + 32768 + t * 8192 + dstB[i], sB[t][i] + ko);
        }
        cp_commit();
    };

    float c1[2][4][4], c3[2][4][4];
#pragma unroll
    for (int a = 0; a < 2; a++)
#pragma unroll
        for (int b = 0; b < 4; b++)
#pragma unroll
            for (int q = 0; q < 4; q++) { c1[a][b][q] = 0.0f; c3[a][b][q] = 0.0f; }

    int m0w = (wid & 3) * 32;
    int n0w = (wid >> 2) * 32;
    const int NC = DIM / BKC;                   // 16

    load(0, 0); load(1, 1); load(2, 2);

#pragma unroll 1
    for (int c = 0; c < NC; c++) {
        cp_wait2();
        __syncthreads();
        int st = c % NSTG;
        uint32_t bA = smb + st * STAGE1;
        uint32_t bAh = bA, bAl = bA + 16384;
        uint32_t b1h = bA + 32768, b1l = bA + 40960;
        uint32_t b3h = bA + 49152, b3l = bA + 57344;
#pragma unroll
        for (int ks = 0; ks < 4; ks++) {
            int k0b = ks * 32;
            uint32_t ah[2][4], al_[2][4];
#pragma unroll
            for (int mg = 0; mg < 2; mg++) {
                int row = m0w + mg * 16 + (lane & 15);
                uint32_t off = SWZ((uint32_t)(row * 128 + k0b + (lane >> 4) * 16));
                ldm4(ah[mg], bAh + off);
                ldm4(al_[mg], bAl + off);
            }
#pragma unroll
            for (int g = 0; g < 2; g++) {
                int nrow = n0w + g * 16 + (lane & 7) + (lane >> 4) * 8;
                uint32_t boff = SWZ((uint32_t)(nrow * 128 + k0b + ((lane >> 3) & 1) * 16));
                uint32_t f1h[4], f1l[4], f3h[4], f3l[4];
                ldm4(f1h, b1h + boff); ldm4(f1l, b1l + boff);
                ldm4(f3h, b3h + boff); ldm4(f3l, b3l + boff);
#pragma unroll
                for (int mg = 0; mg < 2; mg++) {
#pragma unroll
                    for (int sub = 0; sub < 2; sub++) {
                        int ng = g * 2 + sub;
                        mma16816(c1[mg][ng], ah[mg],  f1h + sub * 2);
                        mma16816(c1[mg][ng], ah[mg],  f1l + sub * 2);
                        mma16816(c1[mg][ng], al_[mg], f1h + sub * 2);
                        mma16816(c3[mg][ng], ah[mg],  f3h + sub * 2);
                        mma16816(c3[mg][ng], ah[mg],  f3l + sub * 2);
                        mma16816(c3[mg][ng], al_[mg], f3h + sub * 2);
                    }
                }
            }
        }
        __syncthreads();
        if (c + NSTG < NC) load(c + NSTG, st);
        else cp_commit();
    }

    int goff = g_off[e];
    int t4 = lane >> 2, cpair = (lane & 3) * 2;
#pragma unroll
    for (int mg = 0; mg < 2; mg++) {
#pragma unroll
        for (int half = 0; half < 2; half++) {
            int mi = m0 + m0w + mg * 16 + half * 8 + t4;
            if (mi >= cnt) continue;
            size_t hb = (size_t)(goff + mi) * HP;
#pragma unroll
            for (int ng = 0; ng < 4; ng++) {
                int col = n0 + n0w + ng * 8 + cpair;
                float a0 = c1[mg][ng][half * 2 + 0];
                float a1 = c1[mg][ng][half * 2 + 1];
                float b0 = c3[mg][ng][half * 2 + 0];
                float b1 = c3[mg][ng][half * 2 + 1];
                float h0 = (a0 / (1.0f + __expf(-a0))) * b0;
                float h1 = (a1 / (1.0f + __expf(-a1))) * b1;
                __nv_bfloat16 h0h = __float2bfloat16(h0);
                __nv_bfloat16 h1h = __float2bfloat16(h1);
                __nv_bfloat16 h0l = __float2bfloat16(h0 - __bfloat162float(h0h));
                __nv_bfloat16 h1l = __float2bfloat16(h1 - __bfloat162float(h1h));
                *(uint32_t*)(g_HH + hb + col) = pk(h0h, h1h);
                *(uint32_t*)(g_HL + hb + col) = pk(h0l, h1l);
            }
        }
    }
}

// ---------------- GEMM2: out += wt * (H @ w2^T) ----------------
__global__ __launch_bounds__(256, 1) void gemm2_kernel(float* __restrict__ out) {
    int e = blockIdx.z;
    int cnt = g_count[e];
    int m0 = blockIdx.y * BM;
    if (m0 >= cnt) return;
    int n0 = blockIdx.x * 128;

    extern __shared__ char smraw[];
    uint32_t smb = s2u(smraw);
    int tid = threadIdx.x, wid = tid >> 5, lane = tid & 31;
    int off_e = g_off[e];

    int rA = tid >> 3, c16 = tid & 7;
    uint32_t dstA[4];
    const char* sAh[4]; const char* sAl[4];
    const char* sBh[4]; const char* sBl[4];
#pragma unroll
    for (int i = 0; i < 4; i++) {
        int r = rA + 32 * i;
        uint32_t off = (uint32_t)(r * 128 + c16 * 16);
        dstA[i] = SWZ(off);
        int mi = m0 + r; if (mi >= cnt) mi = cnt - 1;
        size_t ao = (((size_t)(off_e + mi)) * HP + c16 * 8) * 2;
        sAh[i] = (const char*)g_HH + ao;
        sAl[i] = (const char*)g_HL + ao;
        size_t wo = (((size_t)e * DIM + n0 + r) * HP + c16 * 8) * 2;
        sBh[i] = (const char*)g_W2H + wo;
        sBl[i] = (const char*)g_W2L + wo;
    }

    auto load = [&](int kc, int s) {
        uint32_t base = smb + s * STAGE2;
        size_t ko = (size_t)kc * 128;
#pragma unroll
        for (int i = 0; i < 4; i++) {
            cpa16(base + dstA[i], sAh[i] + ko);
            cpa16(base + 16384 + dstA[i], sAl[i] + ko);
            cpa16(base + 32768 + dstA[i], sBh[i] + ko);
            cpa16(base + 49152 + dstA[i], sBl[i] + ko);
        }
        cp_commit();
    };

    float cc[2][8][4];
#pragma unroll
    for (int a = 0; a < 2; a++)
#pragma unroll
        for (int b = 0; b < 8; b++)
#pragma unroll
            for (int q = 0; q < 4; q++) cc[a][b][q] = 0.0f;

    int m0w = (wid & 3) * 32;
    int n0w = (wid >> 2) * 64;
    const int NC = HP / BKC;                    // 44

    load(0, 0); load(1, 1); load(2, 2);

#pragma unroll 1
    for (int c = 0; c < NC; c++) {
        cp_wait2();
        __syncthreads();
        int st = c % NSTG;
        uint32_t bA = smb + st * STAGE2;
        uint32_t bAh = bA, bAl = bA + 16384;
        uint32_t bBh = bA + 32768, bBl = bA + 49152;
#pragma unroll
        for (int ks = 0; ks < 4; ks++) {
            int k0b = ks * 32;
            uint32_t ah[2][4], al_[2][4];
#pragma unroll
            for (int mg = 0; mg < 2; mg++) {
                int row = m0w + mg * 16 + (lane & 15);
                uint32_t off = SWZ((uint32_t)(row * 128 + k0b + (lane >> 4) * 16));
                ldm4(ah[mg], bAh + off);
                ldm4(al_[mg], bAl + off);
            }
#pragma unroll
            for (int g = 0; g < 4; g++) {
                int nrow = n0w + g * 16 + (lane & 7) + (lane >> 4) * 8;
                uint32_t boff = SWZ((uint32_t)(nrow * 128 + k0b + ((lane >> 3) & 1) * 16));
                uint32_t fh[4], fl[4];
                ldm4(fh, bBh + boff); ldm4(fl, bBl + boff);
#pragma unroll
                for (int mg = 0; mg < 2; mg++) {
#pragma unroll
                    for (int sub = 0; sub < 2; sub++) {
                        int ng = g * 2 + sub;
                        mma16816(cc[mg][ng], ah[mg],  fh + sub * 2);
                        mma16816(cc[mg][ng], ah[mg],  fl + sub * 2);
                        mma16816(cc[mg][ng], al_[mg], fh + sub * 2);
                    }
                }
            }
        }
        __syncthreads();
        if (c + NSTG < NC) load(c + NSTG, st);
        else cp_commit();
    }

    int t4 = lane >> 2, cpair = (lane & 3) * 2;
#pragma unroll
    for (int mg = 0; mg < 2; mg++) {
#pragma unroll
        for (int half = 0; half < 2; half++) {
            int mi = m0 + m0w + mg * 16 + half * 8 + t4;
            if (mi >= cnt) continue;
            int tok = g_tokens[e][mi];
            float wt = g_wts[e][mi];
            float* orow = out + (size_t)tok * DIM;
#pragma unroll
            for (int ng = 0; ng < 8; ng++) {
                int col = n0 + n0w + ng * 8 + cpair;
                redadd(&orow[col],     wt * cc[mg][ng][half * 2 + 0]);
                redadd(&orow[col + 1], wt * cc[mg][ng][half * 2 + 1]);
            }
        }
    }
}

// ---------------- launch ----------------
extern "C" void kernel_launch(void* const* d_in, const int* in_sizes, int n_in,
                              void* d_out, int out_size) {
    const float* x  = (const float*)d_in[0];
    const float* gw = (const float*)d_in[1];
    const float* w1 = (const float*)d_in[2];
    const float* w2 = (const float*)d_in[3];
    const float* w3 = (const float*)d_in[4];
    float* out = (float*)d_out;

    cudaFuncSetAttribute(gemm1_kernel, cudaFuncAttributeMaxDynamicSharedMemorySize, NSTG * STAGE1);
    cudaFuncSetAttribute(gemm2_kernel, cudaFuncAttributeMaxDynamicSharedMemorySize, NSTG * STAGE2);

    int nzero = out_size < TOKENS * DIM ? out_size : TOKENS * DIM;
    zero_kernel<<<(nzero + 255) / 256, 256>>>(out, nzero);
    convx_kernel<<<(TOKENS * DIM / 4) / 256, 256>>>(x);
    convw13_kernel<<<(NE * HP * DIM / 4) / 256, 256>>>(w1, w3);
    convw2_kernel<<<(NE * DIM * HP / 4) / 256, 256>>>(w2);
    router_kernel<<<TOKENS * 32 / 256, 256>>>(x, gw);
    scan_kernel<<<1, 32>>>();

    dim3 g1(HP / 64, TOKENS / BM, NE);
    gemm1_kernel<<<g1, 256, NSTG * STAGE1>>>();

    dim3 g2(DIM / 128, TOKENS / BM, NE);
    gemm2_kernel<<<g2, 256, NSTG * STAGE2>>>(out);

    aux_kernel<<<1, 32>>>(out, out_size);
}